// round 8
// baseline (speedup 1.0000x reference)
#include <cuda_runtime.h>
#include <math.h>
#include <stdint.h>

#define LL 2048
#define BB 2
#define DD 256
#define PP 32
#define BL (BB*LL)

// ---------------- scratch ----------------
__device__ __align__(256) float g_content[BL*DD];
__device__ __align__(256) float g_values [BL*DD];
__device__ __align__(256) float g_ctx    [BL*DD];
__device__ __align__(256) float g_ctxavg [BL*DD];
__device__ __align__(256) float g_sgh    [BL*128];
__device__ __align__(256) float g_gate   [BL];
__device__ __align__(256) float g_gcum   [BL];
__device__ __align__(256) float g_cpe    [BL*PP];
__device__ __align__(256) float g_h1     [BL*512];
__device__ __align__(256) float g_Q1     [BL*64];
__device__ __align__(256) float g_K1     [LL*64];
__device__ __align__(256) float g_kvh    [BL*256];
__device__ __align__(256) float g_Q2     [BL*64];
__device__ __align__(256) float g_K2     [BL*64];
__device__ __align__(256) float g_csum   [BB*64*256];
__device__ __align__(256) float g_w2bd   [132*512];
__device__ __align__(256) float g_off    [BL*132];
__device__ __align__(256) float g_comb   [BL*DD];       // atomic-accumulated attn output

__device__ __forceinline__ float gelu_f(float v){
    return 0.5f*v*(1.0f + erff(v*0.70710678118654752f));
}

// ---------------- tf32 / async helpers ----------------
__device__ __forceinline__ uint32_t f2tf(float f){
    uint32_t u; asm("cvt.rna.tf32.f32 %0, %1;" : "=r"(u) : "f"(f)); return u;
}
__device__ __forceinline__ float f2tf_f(float f){ return __uint_as_float(f2tf(f)); }

__device__ __forceinline__ void mma8(float* c,
        uint32_t a0,uint32_t a1,uint32_t a2,uint32_t a3,
        uint32_t b0,uint32_t b1){
    asm volatile("mma.sync.aligned.m16n8k8.row.col.f32.tf32.tf32.f32 "
        "{%0,%1,%2,%3},{%4,%5,%6,%7},{%8,%9},{%0,%1,%2,%3};"
        : "+f"(c[0]),"+f"(c[1]),"+f"(c[2]),"+f"(c[3])
        : "r"(a0),"r"(a1),"r"(a2),"r"(a3),"r"(b0),"r"(b1));
}

__device__ __forceinline__ void cpasync16(void* s, const void* g){
    uint32_t sa = (uint32_t)__cvta_generic_to_shared(s);
    asm volatile("cp.async.cg.shared.global [%0], [%1], 16;" :: "r"(sa), "l"(g));
}
__device__ __forceinline__ void cp_commit(){ asm volatile("cp.async.commit_group;"); }
__device__ __forceinline__ void cp_wait0(){ asm volatile("cp.async.wait_group 0;" ::: "memory"); }

// split-A load
__device__ __forceinline__ float4 ldA4(const float* __restrict__ A,
        const float* __restrict__ A2, int sA, int sA2, int Ksplit, int modA2,
        int row, int col){
    if (!A2 || col < Ksplit)
        return *(const float4*)(A + (size_t)row*sA + col);
    int r2 = modA2 ? (row & 2047) : row;
    return *(const float4*)(A2 + (size_t)r2*sA2 + (col - Ksplit));
}

// kv2 epilogue: build K2 (gate-folded) and Q2 from sp value
__device__ __forceinline__ void kv2_store(int row, int p, float v){
    const float PIf = 3.14159265358979323846f;
    float gv = g_gate[row];
    float s, c;
    sincosf(tanhf(v)*PIf, &s, &c);
    g_K2[(size_t)row*64 + p]      = c*gv;
    g_K2[(size_t)row*64 + 32 + p] = s*gv;
    float inv = rsqrtf(g_gcum[row]) * 0.1767766952966369f; // 1/sqrt(32)
    sincosf(tanhf(g_cpe[(size_t)row*PP + p])*PIf, &s, &c);
    g_Q2[(size_t)row*64 + p]      = c*inv;
    g_Q2[(size_t)row*64 + 32 + p] = s*inv;
}

// ---------------- tf32 GEMM core (register-prefetch pipelined, split-A) ----------------
// emode: 0 plain, 1 gelu, 2 add residual, 3 kv2(K2/Q2 build, no C store)
__device__ __forceinline__ void gemm_core(const float* __restrict__ A,
        const float* __restrict__ A2, int sA, int sA2, int Ksplit, int modA2,
        const float* __restrict__ W, const float* __restrict__ bias,
        const float* __restrict__ addend, float* __restrict__ C,
        int K, int N, int bm, int bn, int emode, int Nlim,
        float (*As)[20], float (*Ws)[20]){
    int t = threadIdx.x;
    int w = t>>5, lane = t&31, gr = lane>>2, ct = lane&3;
    int wm = (w&1)*32, wn = (w>>1)*32;
    int r0 = t>>2, c4 = (t&3)*4;
    float acc[2][4][4];
    #pragma unroll
    for (int mt=0;mt<2;mt++)
        #pragma unroll
        for (int nt=0;nt<4;nt++)
            #pragma unroll
            for (int i=0;i<4;i++) acc[mt][nt][i]=0.f;

    int g0 = bn+r0, g1 = bn+r0+32;
    if (Nlim){ if (g0>=Nlim) g0=Nlim-1; if (g1>=Nlim) g1=Nlim-1; }
    const float* Wr0 = W + (size_t)g0*K + c4;
    const float* Wr1 = W + (size_t)g1*K + c4;
    float4 pa0 = ldA4(A,A2,sA,sA2,Ksplit,modA2, bm+r0,    c4);
    float4 pa1 = ldA4(A,A2,sA,sA2,Ksplit,modA2, bm+r0+32, c4);
    float4 pw0 = *(const float4*)Wr0;
    float4 pw1 = *(const float4*)Wr1;

    for (int k0=0; k0<K; k0+=16){
        As[r0   ][c4+0]=f2tf_f(pa0.x); As[r0   ][c4+1]=f2tf_f(pa0.y);
        As[r0   ][c4+2]=f2tf_f(pa0.z); As[r0   ][c4+3]=f2tf_f(pa0.w);
        As[r0+32][c4+0]=f2tf_f(pa1.x); As[r0+32][c4+1]=f2tf_f(pa1.y);
        As[r0+32][c4+2]=f2tf_f(pa1.z); As[r0+32][c4+3]=f2tf_f(pa1.w);
        Ws[r0   ][c4+0]=f2tf_f(pw0.x); Ws[r0   ][c4+1]=f2tf_f(pw0.y);
        Ws[r0   ][c4+2]=f2tf_f(pw0.z); Ws[r0   ][c4+3]=f2tf_f(pw0.w);
        Ws[r0+32][c4+0]=f2tf_f(pw1.x); Ws[r0+32][c4+1]=f2tf_f(pw1.y);
        Ws[r0+32][c4+2]=f2tf_f(pw1.z); Ws[r0+32][c4+3]=f2tf_f(pw1.w);
        __syncthreads();
        if (k0+16 < K){
            pa0 = ldA4(A,A2,sA,sA2,Ksplit,modA2, bm+r0,    k0+16+c4);
            pa1 = ldA4(A,A2,sA,sA2,Ksplit,modA2, bm+r0+32, k0+16+c4);
            pw0 = *(const float4*)(Wr0 + k0+16);
            pw1 = *(const float4*)(Wr1 + k0+16);
        }
        #pragma unroll
        for (int k8=0;k8<16;k8+=8){
            uint32_t a[2][4];
            #pragma unroll
            for (int mt=0;mt<2;mt++){
                a[mt][0]=__float_as_uint(As[wm+mt*16+gr  ][k8+ct  ]);
                a[mt][1]=__float_as_uint(As[wm+mt*16+gr+8][k8+ct  ]);
                a[mt][2]=__float_as_uint(As[wm+mt*16+gr  ][k8+ct+4]);
                a[mt][3]=__float_as_uint(As[wm+mt*16+gr+8][k8+ct+4]);
            }
            #pragma unroll
            for (int nt=0;nt<4;nt++){
                uint32_t b0=__float_as_uint(Ws[wn+nt*8+gr][k8+ct  ]);
                uint32_t b1=__float_as_uint(Ws[wn+nt*8+gr][k8+ct+4]);
                #pragma unroll
                for (int mt=0;mt<2;mt++)
                    mma8(acc[mt][nt], a[mt][0],a[mt][1],a[mt][2],a[mt][3], b0,b1);
            }
        }
        __syncthreads();
    }
    #pragma unroll
    for (int mt=0;mt<2;mt++){
        #pragma unroll
        for (int nt=0;nt<4;nt++){
            int col = bn + wn + nt*8 + 2*ct;
            if (Nlim && col >= Nlim) continue;
            int rr0 = bm + wm + mt*16 + gr;
            int rr1 = rr0 + 8;
            float b0v = bias[col], b1v = bias[col+1];
            float v00 = acc[mt][nt][0] + b0v;
            float v01 = acc[mt][nt][1] + b1v;
            float v10 = acc[mt][nt][2] + b0v;
            float v11 = acc[mt][nt][3] + b1v;
            if (emode==3){
                kv2_store(rr0, col,   v00);
                kv2_store(rr0, col+1, v01);
                kv2_store(rr1, col,   v10);
                kv2_store(rr1, col+1, v11);
                continue;
            }
            if (emode==1){ v00=gelu_f(v00); v01=gelu_f(v01); v10=gelu_f(v10); v11=gelu_f(v11); }
            if (emode==2){
                v00 += addend[(size_t)rr0*N+col]; v01 += addend[(size_t)rr0*N+col+1];
                v10 += addend[(size_t)rr1*N+col]; v11 += addend[(size_t)rr1*N+col+1];
            }
            C[(size_t)rr0*N+col]   = v00;
            C[(size_t)rr0*N+col+1] = v01;
            C[(size_t)rr1*N+col]   = v10;
            C[(size_t)rr1*N+col+1] = v11;
        }
    }
}

// ---------------- merged GEMM: 5 x-projections + hop layer1 (grid.y = 23) ----------------
__global__ __launch_bounds__(128) void k_gemm_multi_t(const float* __restrict__ x,
        const float* __restrict__ pos,
        const float* __restrict__ w_content, const float* __restrict__ b_content, float* __restrict__ p_content,
        const float* __restrict__ w_val,     const float* __restrict__ b_val,     float* __restrict__ p_values,
        const float* __restrict__ w_ctx,     const float* __restrict__ b_ctx,     float* __restrict__ p_ctx,
        const float* __restrict__ sg_w1,     const float* __restrict__ sg_b1,     float* __restrict__ p_sgh,
        const float* __restrict__ w_cpe,     const float* __restrict__ b_cpe,     float* __restrict__ p_cpe,
        const float* __restrict__ hop_w1,    const float* __restrict__ hop_b1,    float* __restrict__ p_h1){
    __shared__ float As[64][20];
    __shared__ float Ws[64][20];
    int y = blockIdx.y;
    int seg, bn, N, K, Nlim=0, emode=0;
    const float* A2 = nullptr; int modA2 = 0;
    if (y < 12){ seg = y>>2; bn = (y&3)*64; N = 256; K = 256; }
    else if (y < 14){ seg = 3; bn = (y-12)*64; N = 128; K = 256; emode = 1; }
    else if (y == 14){ seg = 4; bn = 0; N = 32; K = 256; Nlim = 32; }
    else { seg = 5; bn = (y-15)*64; N = 512; K = 288; emode = 1; A2 = pos; modA2 = 1; }
    const float* W; const float* Bv; float* C;
    if      (seg==0){ W=w_content; Bv=b_content; C=p_content; }
    else if (seg==1){ W=w_val;     Bv=b_val;     C=p_values;  }
    else if (seg==2){ W=w_ctx;     Bv=b_ctx;     C=p_ctx;     }
    else if (seg==3){ W=sg_w1;     Bv=sg_b1;     C=p_sgh;     }
    else if (seg==4){ W=w_cpe;     Bv=b_cpe;     C=p_cpe;     }
    else            { W=hop_w1;    Bv=hop_b1;    C=p_h1;      }
    gemm_core(x, A2, 256, 32, 256, modA2, W, Bv, nullptr, C,
              K, N, blockIdx.x*64, bn, emode, Nlim, As, Ws);
}

// ---------------- generic single tf32 GEMM ----------------
__global__ __launch_bounds__(128) void k_gemm_t(const float* __restrict__ A,
        const float* __restrict__ A2, int sA, int sA2, int Ksplit,
        const float* __restrict__ W, const float* __restrict__ bias,
        const float* __restrict__ addend, float* __restrict__ C,
        int K, int N, int emode, int Nlim){
    __shared__ float As[64][20];
    __shared__ float Ws[64][20];
    gemm_core(A, A2, sA, sA2, Ksplit, 0, W, bias, addend, C, K, N,
              blockIdx.x*64, blockIdx.y*64, emode, Nlim, As, Ws);
}

// ---------------- prep: K1 trig + block-diag hop_w2 + zero g_comb ----------------
__global__ __launch_bounds__(256) void k_prep(const float* __restrict__ pos,
                                              const float* __restrict__ hop_w2){
    int idx = blockIdx.x*256 + threadIdx.x;
    if (idx < 65536){
        int l = idx >> 5, p = idx & 31;
        float s, c; sincosf(pos[l*PP + p], &s, &c);
        g_K1[l*64 + p] = c; g_K1[l*64 + 32 + p] = s;
    }
    if (idx < 132*512){
        int o = idx >> 9, c = idx & 511;
        int h = o / 33;
        int g = c - (h<<7);
        g_w2bd[idx] = (g >= 0 && g < 128) ? hop_w2[o*128 + g] : 0.f;
    }
    float4 z = make_float4(0.f,0.f,0.f,0.f);
    for (size_t i = (size_t)idx*4; i < (size_t)BL*DD; i += (size_t)264*256*4)
        *(float4*)(g_comb + i) = z;
}

// ---------------- hop epilogue (warp-per-row): off -> coefs/Q1; gate ----------------
__global__ __launch_bounds__(256) void k_hop2(const float* __restrict__ pos,
        const float* __restrict__ sg_w2, const float* __restrict__ sg_b2){
    int wid = threadIdx.x>>5, lane = threadIdx.x&31;
    int row = blockIdx.x*8 + wid;
    int l = row & 2047;
    __shared__ float offs[8][132];
    for (int o=lane; o<132; o+=32) offs[wid][o] = g_off[(size_t)row*132 + o];
    // gate
    float4 hv = ((const float4*)(g_sgh + (size_t)row*128))[lane];
    float4 wv = ((const float4*)sg_w2)[lane];
    float p = hv.x*wv.x + hv.y*wv.y + hv.z*wv.z + hv.w*wv.w;
    #pragma unroll
    for (int o=16;o>0;o>>=1) p += __shfl_down_sync(0xffffffffu, p, o);
    p = __shfl_sync(0xffffffffu, p, 0);
    float gv = 1.0f/(1.0f+expf(-(p + sg_b2[0])));
    if (lane==0) g_gate[row] = gv;
    __syncwarp();
    float coef = 0.f;
    if (lane < 4){
        float ww  = 2.0f/(1.0f+expf(-offs[wid][lane*33+32])) + 0.1f;
        float w2v = ww*ww + 1e-6f;
        float e1 = expf(-0.5f/w2v);
        float e2 = expf(-2.0f/w2v);
        float totw = 1.0f + 2.0f*e1 + 2.0f*e2;
        coef = (1.0f + 2.0f*e1*0.9950041652780258f + 2.0f*e2*0.9800665778412416f)
               / (totw + 1e-6f);
    }
    float c0 = __shfl_sync(0xffffffffu, coef, 0);
    float c1 = __shfl_sync(0xffffffffu, coef, 1);
    float c2 = __shfl_sync(0xffffffffu, coef, 2);
    float c3 = __shfl_sync(0xffffffffu, coef, 3);
    const float PIf = 3.14159265358979323846f;
    float pp = pos[l*PP + lane];
    float s, c, ac, as;
    sincosf(pp + tanhf(offs[wid][lane      ])*PIf, &s, &c); ac  = c0*c; as  = c0*s;
    sincosf(pp + tanhf(offs[wid][33 + lane ])*PIf, &s, &c); ac += c1*c; as += c1*s;
    sincosf(pp + tanhf(offs[wid][66 + lane ])*PIf, &s, &c); ac += c2*c; as += c2*s;
    sincosf(pp + tanhf(offs[wid][99 + lane ])*PIf, &s, &c); ac += c3*c; as += c3*s;
    const float s0 = 0.04419417382415922f; // 1/(4*sqrt(32))
    g_Q1[(size_t)row*64 + lane]      = ac*s0;
    g_Q1[(size_t)row*64 + 32 + lane] = as*s0;
}

// ---------------- chunked ctx_avg scan ----------------
__global__ __launch_bounds__(256) void k_scan1(){ // grid(BB,64)
    int b = blockIdx.x, ch = blockIdx.y, t = threadIdx.x;
    const float* src = g_ctx + ((size_t)(b*2048 + ch*32))*256 + t;
    float s = 0.f;
    #pragma unroll 4
    for (int l=0; l<32; l++) s += src[(size_t)l*256];
    g_csum[(b*64+ch)*256 + t] = s;
}

__global__ __launch_bounds__(256) void k_scan2(){ // grid(BB,64)
    int b = blockIdx.x, ch = blockIdx.y, t = threadIdx.x;
    float run = 0.f;
    for (int j=0; j<ch; j++) run += g_csum[(b*64+j)*256 + t];
    const float* src = g_ctx + ((size_t)(b*2048 + ch*32))*256 + t;
    float* dst = g_ctxavg + ((size_t)(b*2048 + ch*32))*256 + t;
    int base = ch*32;
    #pragma unroll 4
    for (int l=0; l<32; l++){
        run += src[(size_t)l*256];
        dst[(size_t)l*256] = run / (float)(base + l + 1);
    }
}

__global__ void k_scang(){ // grid(BB), 32 thr
    int b = blockIdx.x, lane = threadIdx.x;
    float carry = 0.f;
    for (int l0=0; l0<LL; l0+=32){
        float v = g_gate[b*LL + l0 + lane];
        #pragma unroll
        for (int o=1;o<32;o<<=1){
            float n = __shfl_up_sync(0xffffffffu, v, o);
            if (lane >= o) v += n;
        }
        float tot = __shfl_sync(0xffffffffu, v, 31);
        g_gcum[b*LL + l0 + lane] = fmaxf(v + carry, 1.0f);
        carry += tot;
    }
}

// ---------------- split-KV causal attention (tf32 mma, cp.async, RED.ADD epilogue) ----
#define ATTN_SMEM_FLOATS (4352+2304+4352+16896)
__global__ __launch_bounds__(256,2) void k_attn(){
    int head = blockIdx.z, b = blockIdx.y;
    int id = blockIdx.x;                    // 0..143
    int g = 0;
    while (id >= 2*(g+1)*(g+2)) g++;
    int e  = id - 2*g*(g+1);
    int qt = 4*g + e/(g+1);
    int kc = e - (e/(g+1))*(g+1);
    int kt0 = kc*8;
    int ktend = 2*qt + 2; if (ktend > kt0+8) ktend = kt0+8;

    extern __shared__ float sm[];
    float* Qs  = sm;                    // [64][68]
    float* Ss  = sm + 4352;             // [64][36]
    float* Kb0 = sm + 6656;             // [32][68]
    float* Kb1 = sm + 8832;
    float* Vb0 = sm + 11008;            // [32][264]
    float* Vb1 = sm + 19456;

    const float* Q  = head ? g_Q2 + (size_t)b*LL*64 : g_Q1 + (size_t)b*LL*64;
    const float* Kp = head ? g_K2 + (size_t)b*LL*64 : g_K1;
    const float* V  = head ? g_values + (size_t)b*LL*DD : g_content + (size_t)b*LL*DD;

    int t = threadIdx.x;
    int w = t>>5, lane = t&31, gr = lane>>2, ct = lane&3;

    {
        const float* Kt = Kp + (size_t)kt0*2048;
        const float* Vt = V  + (size_t)kt0*8192;
        #pragma unroll
        for (int i=0;i<2;i++){
            int c = t*2+i; int r=c>>4, c4=(c&15)*4;
            cpasync16(Kb0 + r*68 + c4, Kt + r*64 + c4);
        }
        #pragma unroll
        for (int i=0;i<8;i++){
            int c = t + 256*i; int r=c>>6, c4=(c&63)*4;
            cpasync16(Vb0 + r*264 + c4, Vt + r*256 + c4);
        }
        cp_commit();
    }

    const float* Qt = Q + (size_t)qt*64*64;
    for (int idx=t; idx<4096; idx+=256)
        Qs[(idx>>6)*68 + (idx&63)] = f2tf_f(Qt[idx]);

    float acc[16][4];
    #pragma unroll
    for (int i=0;i<16;i++){ acc[i][0]=0.f; acc[i][1]=0.f; acc[i][2]=0.f; acc[i][3]=0.f; }

    int wmS = (w&3)*16, wnS = (w>>2)*16;
    int wmP = (w&3)*16, wnP = (w>>2)*128;
    int buf = 0;

    for (int kt=kt0; kt<ktend; kt++, buf^=1){
        cp_wait0();
        __syncthreads();
        if (kt+1 < ktend){
            float* Kd = buf ? Kb0 : Kb1;
            float* Vd = buf ? Vb0 : Vb1;
            const float* Kt = Kp + (size_t)(kt+1)*2048;
            const float* Vt = V  + (size_t)(kt+1)*8192;
            #pragma unroll
            for (int i=0;i<2;i++){
                int c = t*2+i; int r=c>>4, c4=(c&15)*4;
                cpasync16(Kd + r*68 + c4, Kt + r*64 + c4);
            }
            #pragma unroll
            for (int i=0;i<8;i++){
                int c = t + 256*i; int r=c>>6, c4=(c&63)*4;
                cpasync16(Vd + r*264 + c4, Vt + r*256 + c4);
            }
            cp_commit();
        }
        const float* Ks = buf ? Kb1 : Kb0;
        const float* Vs = buf ? Vb1 : Vb0;
        // ---- S = Q @ K^T ----
        float cS[2][4];
        #pragma unroll
        for (int nt=0;nt<2;nt++){ cS[nt][0]=0.f; cS[nt][1]=0.f; cS[nt][2]=0.f; cS[nt][3]=0.f; }
        #pragma unroll
        for (int k8=0;k8<64;k8+=8){
            uint32_t a0=__float_as_uint(Qs[(wmS+gr  )*68 + k8+ct  ]);
            uint32_t a1=__float_as_uint(Qs[(wmS+gr+8)*68 + k8+ct  ]);
            uint32_t a2=__float_as_uint(Qs[(wmS+gr  )*68 + k8+ct+4]);
            uint32_t a3=__float_as_uint(Qs[(wmS+gr+8)*68 + k8+ct+4]);
            #pragma unroll
            for (int nt=0;nt<2;nt++){
                uint32_t b0=f2tf(Ks[(wnS+nt*8+gr)*68 + k8+ct  ]);
                uint32_t b1=f2tf(Ks[(wnS+nt*8+gr)*68 + k8+ct+4]);
                mma8(cS[nt], a0,a1,a2,a3, b0,b1);
            }
        }
        bool diag = (kt >= 2*qt);
        #pragma unroll
        for (int nt=0;nt<2;nt++){
            int col0 = wnS + nt*8 + 2*ct;
            int r0 = wmS + gr, r1 = r0 + 8;
            float v00=cS[nt][0], v01=cS[nt][1], v10=cS[nt][2], v11=cS[nt][3];
            if (diag){
                int gcol = kt*32 + col0;
                int grow0 = qt*64 + r0, grow1 = qt*64 + r1;
                if (gcol   > grow0) v00 = 0.f;
                if (gcol+1 > grow0) v01 = 0.f;
                if (gcol   > grow1) v10 = 0.f;
                if (gcol+1 > grow1) v11 = 0.f;
            }
            Ss[r0*36+col0]   = f2tf_f(v00);
            Ss[r0*36+col0+1] = f2tf_f(v01);
            Ss[r1*36+col0]   = f2tf_f(v10);
            Ss[r1*36+col0+1] = f2tf_f(v11);
        }
        __syncthreads();
        // ---- acc += S @ V ----
        #pragma unroll
        for (int k8=0;k8<32;k8+=8){
            uint32_t a0=__float_as_uint(Ss[(wmP+gr  )*36 + k8+ct  ]);
            uint32_t a1=__float_as_uint(Ss[(wmP+gr+8)*36 + k8+ct  ]);
            uint32_t a2=__float_as_uint(Ss[(wmP+gr  )*36 + k8+ct+4]);
            uint32_t a3=__float_as_uint(Ss[(wmP+gr+8)*36 + k8+ct+4]);
            #pragma unroll
            for (int nt=0;nt<16;nt++){
                uint32_t b0=f2tf(Vs[(k8+ct  )*264 + wnP + nt*8 + gr]);
                uint32_t b1=f2tf(Vs[(k8+ct+4)*264 + wnP + nt*8 + gr]);
                mma8(acc[nt], a0,a1,a2,a3, b0,b1);
            }
        }
        __syncthreads();
    }
    float* P = g_comb + ((size_t)b*2048 + (size_t)qt*64)*256;
    #pragma unroll
    for (int nt=0;nt<16;nt++){
        int col = wnP + nt*8 + 2*ct;
        int r0 = wmP + gr, r1 = r0 + 8;
        atomicAdd(P + (size_t)r0*256 + col,     acc[nt][0]);
        atomicAdd(P + (size_t)r0*256 + col + 1, acc[nt][1]);
        atomicAdd(P + (size_t)r1*256 + col,     acc[nt][2]);
        atomicAdd(P + (size_t)r1*256 + col + 1, acc[nt][3]);
    }
}

// ---------------- layernorm ----------------
__global__ __launch_bounds__(256) void k_ln(const float* __restrict__ lng,
                                            const float* __restrict__ lnb){
    int row = blockIdx.x, t = threadIdx.x;
    float c = g_comb[(size_t)row*256 + t];
    float s = c, q = c*c;
    #pragma unroll
    for (int o=16;o>0;o>>=1){
        s += __shfl_down_sync(0xffffffffu, s, o);
        q += __shfl_down_sync(0xffffffffu, q, o);
    }
    __shared__ float ws[8], wq[8];
    __shared__ float mu_s, inv_s;
    if ((t&31)==0){ ws[t>>5]=s; wq[t>>5]=q; }
    __syncthreads();
    if (t==0){
        float S=0.f, Qq=0.f;
        #pragma unroll
        for (int i=0;i<8;i++){ S+=ws[i]; Qq+=wq[i]; }
        float mu = S*(1.0f/256.0f);
        float var = Qq*(1.0f/256.0f) - mu*mu;
        mu_s = mu; inv_s = rsqrtf(var + 1e-5f);
    }
    __syncthreads();
    float v = (c - mu_s)*inv_s*lng[t] + lnb[t];
    g_ctx[(size_t)row*DD + t] = v;
}

// ---------------- launch ----------------
extern "C" void kernel_launch(void* const* d_in, const int* in_sizes, int n_in,
                              void* d_out, int out_size){
    const float* x         = (const float*)d_in[0];
    const float* pos       = (const float*)d_in[1];
    const float* w_content = (const float*)d_in[2];
    const float* b_content = (const float*)d_in[3];
    const float* hop_w1    = (const float*)d_in[4];
    const float* hop_b1    = (const float*)d_in[5];
    const float* hop_w2    = (const float*)d_in[6];
    const float* hop_b2    = (const float*)d_in[7];
    const float* w_cpe     = (const float*)d_in[8];
    const float* b_cpe     = (const float*)d_in[9];
    const float* w_val     = (const float*)d_in[10];
    const float* b_val     = (const float*)d_in[11];
    const float* w_ctx     = (const float*)d_in[12];
    const float* b_ctx     = (const float*)d_in[13];
    const float* kv_w1     = (const float*)d_in[14];
    const float* kv_b1     = (const float*)d_in[15];
    const float* kv_w2     = (const float*)d_in[16];
    const float* kv_b2     = (const float*)d_in[17];
    const float* sg_w1     = (const float*)d_in[18];
    const float* sg_b1     = (const float*)d_in[19];
    const float* sg_w2     = (const float*)d_in[20];
    const float* sg_b2     = (const float*)d_in[21];
    const float* ln_g      = (const float*)d_in[22];
    const float* ln_b      = (const float*)d_in[23];
    const float* w_out     = (const float*)d_in[24];
    const float* b_out     = (const float*)d_in[25];
    float* out = (float*)d_out;

    float *p_content, *p_values, *p_ctx, *p_ctxavg, *p_sgh, *p_cpe, *p_h1,
          *p_kvh, *p_w2bd, *p_off;
    cudaGetSymbolAddress((void**)&p_content, g_content);
    cudaGetSymbolAddress((void**)&p_values , g_values );
    cudaGetSymbolAddress((void**)&p_ctx    , g_ctx    );
    cudaGetSymbolAddress((void**)&p_ctxavg , g_ctxavg );
    cudaGetSymbolAddress((void**)&p_sgh    , g_sgh    );
    cudaGetSymbolAddress((void**)&p_cpe    , g_cpe    );
    cudaGetSymbolAddress((void**)&p_h1     , g_h1     );
    cudaGetSymbolAddress((void**)&p_kvh    , g_kvh    );
    cudaGetSymbolAddress((void**)&p_w2bd   , g_w2bd   );
    cudaGetSymbolAddress((void**)&p_off    , g_off    );

    cudaFuncSetAttribute(k_attn, cudaFuncAttributeMaxDynamicSharedMemorySize,
                         ATTN_SMEM_FLOATS*4);

    k_prep<<<264, 256>>>(pos, hop_w2);

    k_gemm_multi_t<<<dim3(64,23), 128>>>(x, pos,
        w_content, b_content, p_content,
        w_val,     b_val,     p_values,
        w_ctx,     b_ctx,     p_ctx,
        sg_w1,     sg_b1,     p_sgh,
        w_cpe,     b_cpe,     p_cpe,
        hop_w1,    hop_b1,    p_h1);

    // hop layer 2 as block-diagonal GEMM
    k_gemm_t<<<dim3(64,3), 128>>>(p_h1, nullptr, 512, 0, 0,
        p_w2bd, hop_b2, nullptr, p_off, 512, 132, 0, 132);

    k_hop2<<<BL/8, 256>>>(pos, sg_w2, sg_b2);

    k_scan1<<<dim3(BB,64), 256>>>();
    k_scan2<<<dim3(BB,64), 256>>>();
    k_scang<<<BB, 32>>>();

    // kv MLP: storage_in = [x, ctx_avg] via split-A; kv2 builds K2/Q2 in epilogue
    k_gemm_t<<<dim3(64,4), 128>>>(x, p_ctxavg, 256, 256, 256,
        kv_w1, kv_b1, nullptr, p_kvh, 512, 256, 1, 0);
    k_gemm_t<<<dim3(64,1), 128>>>(p_kvh, nullptr, 256, 0, 0,
        kv_w2, kv_b2, nullptr, nullptr, 256, 32, 3, 32);

    k_attn<<<dim3(144, BB, 2), 256, ATTN_SMEM_FLOATS*4>>>();

    k_ln<<<BL, 256>>>(ln_g, ln_b);
    k_gemm_t<<<dim3(64,4), 128>>>(p_ctx, nullptr, 256, 0, 0,
        w_out, b_out, x, out, 256, 256, 2, 0);
}